// round 15
// baseline (speedup 1.0000x reference)
#include <cuda_runtime.h>
#include <cuda_fp16.h>
#include <cstdint>

#define HID 1024
#define VOC 32000
#define NL  3
#define NB  64
#define NT  32
#define K3H (3*HID)

// ---------------- device scratch (static, allocation-free) ----------------
__device__ __align__(16) __half g_Wih16[NL * K3H * HID];
__device__ __align__(16) __half g_Whh16[NL * K3H * HID];
__device__ __align__(16) __half g_Wout16[VOC * HID];
__device__ __align__(16) __half g_x16a[NB * NT * HID];
__device__ __align__(16) __half g_x16b[NB * NT * HID];
__device__ __align__(16) float  g_xp[NB * NT * K3H];
__device__ __align__(16) __half g_h16L[NL * 2 * NB * HID];   // per-layer ping-pong h

// grid barrier state (generation-based; never needs host reset)
__device__ unsigned g_bar_cnt = 0;
__device__ unsigned g_bar_gen = 0;

// ---------------- helpers ----------------
__device__ __forceinline__ uint32_t smem_u32(const void* p) {
    return (uint32_t)__cvta_generic_to_shared(p);
}
__device__ __forceinline__ void cp16(uint32_t d, const void* s) {
    asm volatile("cp.async.cg.shared.global [%0], [%1], 16;\n" :: "r"(d), "l"(s));
}
__device__ __forceinline__ void cp_commit() {
    asm volatile("cp.async.commit_group;\n" ::: "memory");
}
__device__ __forceinline__ void mma16816(float* c, const uint32_t* a, const uint32_t* b) {
    asm volatile(
        "mma.sync.aligned.m16n8k16.row.col.f32.f16.f16.f32 "
        "{%0,%1,%2,%3},{%4,%5,%6,%7},{%8,%9},{%0,%1,%2,%3};\n"
        : "+f"(c[0]), "+f"(c[1]), "+f"(c[2]), "+f"(c[3])
        : "r"(a[0]), "r"(a[1]), "r"(a[2]), "r"(a[3]), "r"(b[0]), "r"(b[1]));
}
__device__ __forceinline__ void ldsm4(uint32_t& r0, uint32_t& r1, uint32_t& r2, uint32_t& r3,
                                      uint32_t a) {
    asm volatile("ldmatrix.sync.aligned.m8n8.x4.shared.b16 {%0,%1,%2,%3},[%4];\n"
                 : "=r"(r0), "=r"(r1), "=r"(r2), "=r"(r3) : "r"(a));
}
__device__ __forceinline__ void ldsm2(uint32_t& r0, uint32_t& r1, uint32_t a) {
    asm volatile("ldmatrix.sync.aligned.m8n8.x2.shared.b16 {%0,%1},[%2];\n"
                 : "=r"(r0), "=r"(r1) : "r"(a));
}

// ---------------- f32 -> f16 weight converts ----------------
__global__ void k_cvt_ihhh(const float* __restrict__ W_ih, const float* __restrict__ W_hh) {
    const int n1 = NL * K3H * HID;
    int i = (blockIdx.x * 256 + threadIdx.x) * 4;
    const float* src;
    __half* dst;
    int j;
    if (i < n1) { src = W_ih; dst = g_Wih16; j = i; }
    else        { src = W_hh; dst = g_Whh16; j = i - n1; }
    float4 v = *(const float4*)(src + j);
    *(__half2*)(dst + j)     = __floats2half2_rn(v.x, v.y);
    *(__half2*)(dst + j + 2) = __floats2half2_rn(v.z, v.w);
}
__global__ void k_cvt_out(const float* __restrict__ src) {
    int i = (blockIdx.x * 256 + threadIdx.x) * 4;
    float4 v = *(const float4*)(src + i);
    *(__half2*)(g_Wout16 + i)     = __floats2half2_rn(v.x, v.y);
    *(__half2*)(g_Wout16 + i + 2) = __floats2half2_rn(v.z, v.w);
}

// ---------------- embedding + relu -> x16a ----------------
__global__ void k_embed(const float* __restrict__ emb, const int* __restrict__ target) {
    int row = blockIdx.x;           // 0..NB*NT-1
    int b = row >> 5, t = row & 31; // NT = 32
    int id = (t == 0) ? 0 : target[b * NT + t - 1];
    const float* src = emb + (size_t)id * HID;
    __half* dst = g_x16a + (size_t)row * HID;
    int i = threadIdx.x * 4;
    float4 v = *(const float4*)(src + i);
    *(__half2*)(dst + i)     = __floats2half2_rn(fmaxf(v.x, 0.f), fmaxf(v.y, 0.f));
    *(__half2*)(dst + i + 2) = __floats2half2_rn(fmaxf(v.z, 0.f), fmaxf(v.w, 0.f));
}

// ---------------- fp16 MMA GEMM: C[M,N] = A[M,K] @ B[N,K]^T + bias ----------------
#define G2_STG   (128 * 40)
#define G2_SMEM  (4 * 2 * G2_STG * 2)
__global__ __launch_bounds__(256, 2) void k_gemm2(int aSel, int bSel,
                                                  const float* __restrict__ bias,
                                                  int cSel, float* __restrict__ Cext, int ldc) {
    extern __shared__ __align__(16) char g2_raw[];
    __half* smA = (__half*)g2_raw;
    __half* smB = smA + 4 * G2_STG;

    const __half* A  = (aSel == 0) ? g_x16a : g_x16b;
    const __half* Bw = (bSel < 3) ? (g_Wih16 + (size_t)bSel * K3H * HID) : g_Wout16;
    float* C = (cSel == 0) ? g_xp : Cext;

    const int tid = threadIdx.x;
    const int bn = blockIdx.x, bm = blockIdx.y;
    const int lane = tid & 31, warp = tid >> 5;
    const int g = lane >> 2, tg = lane & 3;
    const int wy = warp >> 2, wx = warp & 3;

    const int ldr = tid >> 2;
    const int seg = (tid & 3) * 8;
    const __half* gA0 = A  + (size_t)(bm * 128 + ldr) * HID + seg;
    const __half* gA1 = A  + (size_t)(bm * 128 + 64 + ldr) * HID + seg;
    const __half* gB0 = Bw + (size_t)(bn * 128 + ldr) * HID + seg;
    const __half* gB1 = Bw + (size_t)(bn * 128 + 64 + ldr) * HID + seg;
    const uint32_t dA0 = smem_u32(&smA[ldr * 40 + seg]);
    const uint32_t dA1 = smem_u32(&smA[(64 + ldr) * 40 + seg]);
    const uint32_t dB0 = smem_u32(&smB[ldr * 40 + seg]);
    const uint32_t dB1 = smem_u32(&smB[(64 + ldr) * 40 + seg]);
    const int stgB = G2_STG * 2;

    uint32_t aoff[4], boff[2];
#pragma unroll
    for (int mt = 0; mt < 4; ++mt)
        aoff[mt] = ((wy * 64 + mt * 16 + (lane & 15)) * 40 + (lane >> 4) * 8) * 2;
#pragma unroll
    for (int np = 0; np < 2; ++np)
        boff[np] = ((wx * 32 + np * 16 + (lane & 7) + ((lane & 16) >> 1)) * 40 +
                    ((lane >> 3) & 1) * 8) * 2;
    const uint32_t smA_u = smem_u32(smA);
    const uint32_t smB_u = smem_u32(smB);

    const int NK = HID / 32;

#pragma unroll
    for (int s = 0; s < 3; ++s) {
        cp16(dA0 + s * stgB, gA0 + s * 32);
        cp16(dA1 + s * stgB, gA1 + s * 32);
        cp16(dB0 + s * stgB, gB0 + s * 32);
        cp16(dB1 + s * stgB, gB1 + s * 32);
        cp_commit();
    }

    float acc[4][4][4] = {};
    for (int kc = 0; kc < NK; ++kc) {
        asm volatile("cp.async.wait_group 2;\n" ::: "memory");
        __syncthreads();
        if (kc + 3 < NK) {
            int s = (kc + 3) & 3;
            cp16(dA0 + s * stgB, gA0 + (kc + 3) * 32);
            cp16(dA1 + s * stgB, gA1 + (kc + 3) * 32);
            cp16(dB0 + s * stgB, gB0 + (kc + 3) * 32);
            cp16(dB1 + s * stgB, gB1 + (kc + 3) * 32);
        }
        cp_commit();

        const uint32_t Abase = smA_u + (kc & 3) * stgB;
        const uint32_t Bbase = smB_u + (kc & 3) * stgB;
#pragma unroll
        for (int kk = 0; kk < 32; kk += 16) {
            uint32_t a[4][4], bb[4][2];
#pragma unroll
            for (int mt = 0; mt < 4; ++mt)
                ldsm4(a[mt][0], a[mt][1], a[mt][2], a[mt][3], Abase + aoff[mt] + kk * 2);
#pragma unroll
            for (int np = 0; np < 2; ++np)
                ldsm4(bb[np * 2][0], bb[np * 2][1], bb[np * 2 + 1][0], bb[np * 2 + 1][1],
                      Bbase + boff[np] + kk * 2);
#pragma unroll
            for (int mt = 0; mt < 4; ++mt)
#pragma unroll
                for (int nt = 0; nt < 4; ++nt)
                    mma16816(acc[mt][nt], a[mt], bb[nt]);
        }
    }

#pragma unroll
    for (int mt = 0; mt < 4; ++mt) {
#pragma unroll
        for (int nt = 0; nt < 4; ++nt) {
            int row = bm * 128 + wy * 64 + mt * 16 + g;
            int col = bn * 128 + wx * 32 + nt * 8 + tg * 2;
            float b0 = bias[col], b1 = bias[col + 1];
            *(float2*)&C[(size_t)row * ldc + col] =
                make_float2(acc[mt][nt][0] + b0, acc[mt][nt][1] + b1);
            *(float2*)&C[(size_t)(row + 8) * ldc + col] =
                make_float2(acc[mt][nt][2] + b0, acc[mt][nt][3] + b1);
        }
    }
}

// ---------------- 3-layer wavefront GRU: all layers + timesteps in ONE kernel ----------------
// 64 blocks x 256 threads. Block cblk owns hidden cols [cblk*16,+16) (48 gate rows)
// of EVERY layer. Wall step s: layer l processes t=s-l (if in range). l>=1 units run
// two passes (x-part vs W_ih, h-part vs W_hh; separate accs because n-gate applies r
// only to the h part). W slices streamed from L2 through the same chunk pipeline as A.
// 34 grid barriers total (vs 96).
#define WV_ACH 2560                  // 64x40 halves per A chunk
#define WV_BCH 1920                  // 48x40 halves per B chunk
#define WV_AS  (12 * WV_ACH)
#define WV_BS  (12 * WV_BCH)
#define WAVE_SMEM (WV_AS*2 + WV_BS*2 + 3200*4 + 3200*4 + 3072*4 + 3072*4)
__global__ __launch_bounds__(256) void k_gru_wave(const float* __restrict__ bih_g,
                                                  const float* __restrict__ bhh_g,
                                                  const float* __restrict__ enc,
                                                  float* __restrict__ out) {
    extern __shared__ __align__(16) char smem_raw[];
    __half* As   = (__half*)smem_raw;            // 12 chunk bufs 64x40
    __half* Bs   = As + WV_AS;                   // 12 chunk bufs 48x40
    float*  hp_s = (float*)(Bs + WV_BS);         // 64 x 50
    float*  xq_s = hp_s + 3200;                  // 64 x 50
    float*  xp_s = xq_s + 3200;                  // 64 x 48 (layer-0 precomputed xp)
    float*  h_own = xp_s + 3072;                 // [3][64*16] fp32 h columns

    const int tid = threadIdx.x;
    const int cblk = blockIdx.x;                 // 0..63
    const int lane = tid & 31, warp = tid >> 5;
    const int g = lane >> 2, tg = lane & 3;
    const int wm = warp >> 1, wn = warp & 1;

    // loaders
    const int ldr = tid >> 2;                    // 0..63 A row
    const int seg = (tid & 3) * 8;
    const bool doB = tid < 192;
    const int brow = tid >> 2;                   // 0..47 when doB
    const int bgate = brow >> 4;
    const size_t bgrow = (size_t)(bgate * HID + cblk * 16 + (brow & 15));

    const uint32_t As_u = smem_u32(As);
    const uint32_t Bs_u = smem_u32(Bs);
    const uint32_t dA = As_u + (ldr * 40 + seg) * 2;
    const uint32_t dB = Bs_u + (brow * 40 + seg) * 2;

    // ldmatrix offsets (A 64x40, B 48x40)
    const uint32_t aoff  = ((wm * 16 + (lane & 15)) * 40 + (lane >> 4) * 8) * 2;
    const uint32_t boff4 = ((wn * 24 + (lane & 7) + ((lane & 16) >> 1)) * 40 +
                            ((lane >> 3) & 1) * 8) * 2;
    const uint32_t boff2 = ((wn * 24 + 16 + (lane & 7)) * 40 + ((lane >> 3) & 1) * 8) * 2;

    // h0 init: all 3 layers, own 16 columns (fp16 global parity-0 + fp32 smem)
    for (int i = tid; i < 3 * 1024; i += 256) {
        int l = i >> 10, r = i & 1023;
        int b = r >> 4, jl = r & 15;
        float v = enc[(size_t)l * NB * HID + (size_t)b * HID + cblk * 16 + jl];
        h_own[i] = v;
        g_h16L[((size_t)l * 2) * NB * HID + (size_t)b * HID + cblk * 16 + jl] = __float2half(v);
    }

    unsigned bar_t = *(volatile unsigned*)&g_bar_gen;
    __syncthreads();
    bar_t++;
    if (tid == 0) {
        __threadfence();
        unsigned a = atomicAdd(&g_bar_cnt, 1);
        if (a == 63) { g_bar_cnt = 0; __threadfence(); atomicExch(&g_bar_gen, bar_t); }
        else { while (*(volatile unsigned*)&g_bar_gen < bar_t) { __nanosleep(32); } }
        __threadfence();
    }
    __syncthreads();

    // per-layer gate biases (jl fixed per thread)
    const int jl = tid & 15;
    const int j = cblk * 16 + jl;
    float addR[3], addZ[3], addNx[3], addNh[3];
#pragma unroll
    for (int l = 0; l < 3; ++l) {
        const float* bi = bih_g + (size_t)l * K3H;
        const float* bh = bhh_g + (size_t)l * K3H;
        if (l == 0) { addR[l] = bh[j]; addZ[l] = bh[HID + j]; addNx[l] = 0.f; }
        else { addR[l] = bi[j] + bh[j]; addZ[l] = bi[HID + j] + bh[HID + j];
               addNx[l] = bi[2 * HID + j]; }
        addNh[l] = bh[2 * HID + j];
    }

    // streamed GEMM pass: acc += A[64,1024] @ Wslice48^T  (A rows: base + ldr*strideA)
    auto run_pass = [&](const __half* baseA, size_t strideA, const __half* Wbase,
                        float (*acc)[4], bool xpPre, int tXp) {
        const __half* gA = baseA + (size_t)ldr * strideA + seg;
        const __half* gB = Wbase + bgrow * HID + seg;   // seg == bseg layout
        // optional layer-0 xp prefetch rides in the first commit group
        if (xpPre) {
            for (int e = tid; e < 768; e += 256) {
                int b = e / 12, rem = e % 12;
                int gate = rem >> 2, sg4 = (rem & 3) * 4;
                cp16(smem_u32(&xp_s[b * 48 + gate * 16 + sg4]),
                     g_xp + ((size_t)(b * NT + tXp)) * K3H + gate * HID + cblk * 16 + sg4);
            }
        }
#pragma unroll
        for (int sp = 0; sp < 2; ++sp) {
#pragma unroll
            for (int c = 0; c < 4; ++c) {
                int ch = sp * 4 + c;
                cp16(dA + ch * (WV_ACH * 2), gA + ch * 32);
                if (doB) cp16(dB + ch * (WV_BCH * 2), gB + ch * 32);
            }
            cp_commit();
        }
        for (int sb = 0; sb < 8; ++sb) {
            asm volatile("cp.async.wait_group 1;\n" ::: "memory");
            __syncthreads();
            if (sb + 2 < 8) {
                int sbuf = (sb + 2) % 3;
#pragma unroll
                for (int c = 0; c < 4; ++c) {
                    int slot = sbuf * 4 + c, ch = (sb + 2) * 4 + c;
                    cp16(dA + slot * (WV_ACH * 2), gA + ch * 32);
                    if (doB) cp16(dB + slot * (WV_BCH * 2), gB + ch * 32);
                }
            }
            cp_commit();
            const int sbase = (sb % 3) * 4;
#pragma unroll
            for (int cc = 0; cc < 4; ++cc) {
                const uint32_t Ab  = As_u + (sbase + cc) * (WV_ACH * 2) + aoff;
                const uint32_t Bb  = Bs_u + (sbase + cc) * (WV_BCH * 2) + boff4;
                const uint32_t Bb2 = Bs_u + (sbase + cc) * (WV_BCH * 2) + boff2;
#pragma unroll
                for (int kk = 0; kk < 32; kk += 16) {
                    uint32_t a[4], bb[3][2];
                    ldsm4(a[0], a[1], a[2], a[3], Ab + kk * 2);
                    ldsm4(bb[0][0], bb[0][1], bb[1][0], bb[1][1], Bb + kk * 2);
                    ldsm2(bb[2][0], bb[2][1], Bb2 + kk * 2);
#pragma unroll
                    for (int nt = 0; nt < 3; ++nt) mma16816(acc[nt], a, bb[nt]);
                }
            }
        }
        __syncthreads();   // all reads of A/B bufs done before next pass overwrites
    };

    auto stage = [&](float (*acc)[4], float* dst) {
#pragma unroll
        for (int nt = 0; nt < 3; ++nt) {
            int row = wm * 16 + g, col = wn * 24 + nt * 8 + tg * 2;
            *(float2*)&dst[row * 50 + col]       = make_float2(acc[nt][0], acc[nt][1]);
            *(float2*)&dst[(row + 8) * 50 + col] = make_float2(acc[nt][2], acc[nt][3]);
        }
    };

    for (int s = 0; s < NT + NL - 1; ++s) {
#pragma unroll
        for (int l = 0; l < NL; ++l) {
            int t = s - l;
            if (t < 0 || t >= NT) continue;
            const __half* Wih = g_Wih16 + (size_t)l * K3H * HID;
            const __half* Whh = g_Whh16 + (size_t)l * K3H * HID;
            const __half* hin = g_h16L + ((size_t)(l * 2 + (t & 1))) * NB * HID;
            __half* hout = g_h16L + ((size_t)(l * 2 + ((t + 1) & 1))) * NB * HID;
            __half* ydst = (l == 1) ? g_x16a : g_x16b;

            float accH[3][4] = {};
            if (l == 0) {
                run_pass(hin, HID, Whh, accH, true, t);
                stage(accH, hp_s);
            } else {
                float accX[3][4] = {};
                const __half* ysrc = (l == 1) ? g_x16b : g_x16a;
                run_pass(ysrc + (size_t)t * HID, (size_t)NT * HID, Wih, accX, false, 0);
                run_pass(hin, HID, Whh, accH, false, 0);
                stage(accX, xq_s);
                stage(accH, hp_s);
            }
            __syncthreads();

            // fused gate epilogue (own 16 columns of this layer)
            float* ho_l = h_own + l * 1024;
#pragma unroll
            for (int i = 0; i < 4; ++i) {
                int idx = tid + i * 256;
                int b = idx >> 4;
                float hpr = hp_s[b * 50 + jl];
                float hpz = hp_s[b * 50 + 16 + jl];
                float hpn = hp_s[b * 50 + 32 + jl];
                float xr, xz, xn;
                if (l == 0) {
                    xr = xp_s[b * 48 + jl];
                    xz = xp_s[b * 48 + 16 + jl];
                    xn = xp_s[b * 48 + 32 + jl];
                } else {
                    xr = xq_s[b * 50 + jl];
                    xz = xq_s[b * 50 + 16 + jl];
                    xn = xq_s[b * 50 + 32 + jl];
                }
                float r = 1.f / (1.f + __expf(-(xr + hpr + addR[l])));
                float z = 1.f / (1.f + __expf(-(xz + hpz + addZ[l])));
                float nn = tanhf(xn + addNx[l] + r * (hpn + addNh[l]));
                float ho = ho_l[idx];
                float hnew = (1.f - z) * nn + z * ho;
                ho_l[idx] = hnew;
                __half h16 = __float2half(hnew);
                hout[(size_t)b * HID + j] = h16;
                ydst[((size_t)(b * NT + t)) * HID + j] = h16;
                if (t == NT - 1)
                    out[(size_t)NB * NT * VOC + (size_t)l * NB * HID + (size_t)b * HID + j] = hnew;
            }
            __syncthreads();
        }

        // wall-step grid barrier
        bar_t++;
        if (tid == 0) {
            __threadfence();
            unsigned a = atomicAdd(&g_bar_cnt, 1);
            if (a == 63) { g_bar_cnt = 0; __threadfence(); atomicExch(&g_bar_gen, bar_t); }
            else { while (*(volatile unsigned*)&g_bar_gen < bar_t) { __nanosleep(32); } }
            __threadfence();
        }
        __syncthreads();
    }
}

// ---------------- in-place log_softmax over V per row ----------------
__global__ __launch_bounds__(1024) void k_logsoftmax(float* __restrict__ p) {
    float* base = p + (size_t)blockIdx.x * VOC;
    const int tid = threadIdx.x;
    const int warp = tid >> 5, lane = tid & 31;
    __shared__ float red[32];

    float v[32];
    float m = -1e30f;
#pragma unroll
    for (int i = 0; i < 32; ++i) {
        int idx = tid + i * 1024;
        v[i] = (idx < VOC) ? base[idx] : -1e30f;
        m = fmaxf(m, v[i]);
    }
#pragma unroll
    for (int off = 16; off; off >>= 1) m = fmaxf(m, __shfl_xor_sync(0xffffffffu, m, off));
    if (lane == 0) red[warp] = m;
    __syncthreads();
    if (warp == 0) {
        float x = red[lane];
#pragma unroll
        for (int off = 16; off; off >>= 1) x = fmaxf(x, __shfl_xor_sync(0xffffffffu, x, off));
        red[lane] = x;
    }
    __syncthreads();
    m = red[0];
    __syncthreads();

    float s = 0.f;
#pragma unroll
    for (int i = 0; i < 32; ++i) s += __expf(v[i] - m);
#pragma unroll
    for (int off = 16; off; off >>= 1) s += __shfl_xor_sync(0xffffffffu, s, off);
    if (lane == 0) red[warp] = s;
    __syncthreads();
    if (warp == 0) {
        float x = red[lane];
#pragma unroll
        for (int off = 16; off; off >>= 1) x += __shfl_xor_sync(0xffffffffu, x, off);
        red[lane] = x;
    }
    __syncthreads();
    s = red[0];

    float lse = m + logf(s);
#pragma unroll
    for (int i = 0; i < 32; ++i) {
        int idx = tid + i * 1024;
        if (idx < VOC) base[idx] = v[i] - lse;
    }
}

// ---------------- launch ----------------
extern "C" void kernel_launch(void* const* d_in, const int* in_sizes, int n_in,
                              void* d_out, int out_size) {
    const float* enc_hidden = (const float*)d_in[1];
    const int*   target     = (const int*)d_in[2];
    const float* emb        = (const float*)d_in[3];
    const float* W_ih       = (const float*)d_in[4];
    const float* W_hh       = (const float*)d_in[5];
    const float* b_ih       = (const float*)d_in[6];
    const float* b_hh       = (const float*)d_in[7];
    const float* W_out      = (const float*)d_in[8];
    const float* b_out      = (const float*)d_in[9];
    float* out = (float*)d_out;

    cudaFuncSetAttribute(k_gru_wave, cudaFuncAttributeMaxDynamicSharedMemorySize, WAVE_SMEM);
    cudaFuncSetAttribute(k_gemm2, cudaFuncAttributeMaxDynamicSharedMemorySize, G2_SMEM);

    const int n1 = NL * K3H * HID;
    const int n2 = VOC * HID;

    k_cvt_ihhh<<<(2 * n1 / 4) / 256, 256>>>(W_ih, W_hh);                 // 0
    k_embed<<<NB * NT, 256>>>(emb, target);                              // 1
    k_gemm2<<<dim3(K3H / 128, (NB * NT) / 128), 256, G2_SMEM>>>(         // 2: layer-0 xp
        0, 0, b_ih, 0, nullptr, K3H);
    k_gru_wave<<<64, 256, WAVE_SMEM>>>(b_ih, b_hh, enc_hidden, out);     // 3 (profiled)
    k_cvt_out<<<(n2 / 4) / 256, 256>>>(W_out);                           // 4

    // output GEMM (logits into d_out) + log_softmax in place
    k_gemm2<<<dim3(VOC / 128, (NB * NT) / 128), 256, G2_SMEM>>>(1, 3, b_out, 1, out, VOC);
    k_logsoftmax<<<NB * NT, 1024>>>(out);
}